// round 1
// baseline (speedup 1.0000x reference)
#include <cuda_runtime.h>
#include <cuda_bf16.h>
#include <cstddef>

// Problem constants
#define BB 2
#define CC 256
#define HH 64
#define WW 64
#define PP 4096          // H*W
#define NSET 128
#define GG 64            // groups
#define CGC 4            // channels per group
#define KTAP 3

// ---------------- scratch (device globals; no allocs allowed) ----------------
__device__ float g_mean[BB * CC];
__device__ float g_sca[BB * CC];
__device__ float g_ydw1[BB * CC * PP];
__device__ float g_yc1a[BB * CC * PP];
__device__ float g_attlin[BB * NSET * PP];
__device__ float g_x1[BB * CC * PP];
__device__ float g_uf[BB * CC * PP];
__device__ float g_l0[BB * CC * PP];
__device__ float g_l1[BB * CC * PP];
__device__ float g_lka[BB * CC * PP];
__device__ float g_tg[BB * 16 * PP];
__device__ float g_att[BB * NSET * PP];
__device__ float g_xh[BB * CC * PP];
__device__ float g_x2[BB * CC * PP];
__device__ float g_z[BB * CC * PP];

// ---------------- mean over H,W per (b,c) ----------------
__global__ void __launch_bounds__(256) meankern(const float* __restrict__ X,
                                                float* __restrict__ M) {
    int bc = blockIdx.x;
    const float* xp = X + (size_t)bc * PP;
    float s = 0.f;
    for (int p = threadIdx.x; p < PP; p += 256) s += xp[p];
    __shared__ float red[256];
    red[threadIdx.x] = s;
    __syncthreads();
    for (int st = 128; st > 0; st >>= 1) {
        if (threadIdx.x < st) red[threadIdx.x] += red[threadIdx.x + st];
        __syncthreads();
    }
    if (threadIdx.x == 0) M[bc] = red[0] * (1.f / PP);
}

// ---------------- sca = 1x1 conv on the mean vector ----------------
__global__ void __launch_bounds__(256) scakern(const float* __restrict__ M,
                                               const float* __restrict__ Wsca,
                                               const float* __restrict__ Bsca,
                                               float* __restrict__ SCA) {
    int b = blockIdx.x;
    int o = threadIdx.x;
    __shared__ float m[CC];
    m[o] = M[b * CC + o];
    __syncthreads();
    float s = Bsca[o];
    const float* wr = Wsca + (size_t)o * CC;
    for (int c = 0; c < CC; c++) s += wr[c] * m[c];
    SCA[b * CC + o] = s;
}

// ---------------- generic 1x1 conv GEMM: Y[b][m][p] = sum_k W[m][k] X[b][k][p] (+bias) -----
__global__ void __launch_bounds__(256) gemm1x1(const float* __restrict__ Wm,
                                               const float* __restrict__ X,
                                               const float* __restrict__ bias,
                                               float* __restrict__ Y,
                                               int M, int K) {
    __shared__ float As[16][68];   // [k][m], padded row for alignment + fewer conflicts
    __shared__ float Bs[16][64];   // [k][n]
    int b = blockIdx.z;
    int m0 = blockIdx.y << 6, n0 = blockIdx.x << 6;
    const float* Xb = X + (size_t)b * K * PP;
    float* Yb = Y + (size_t)b * M * PP;
    int tid = threadIdx.x;
    int tx = tid & 15, ty = tid >> 4;
    int arow = tid >> 2, ak = (tid & 3) << 2;
    int brow = tid >> 4, bn = (tid & 15) << 2;
    float acc[4][4] = {};
    for (int k0 = 0; k0 < K; k0 += 16) {
        float4 av = *(const float4*)&Wm[(size_t)(m0 + arow) * K + k0 + ak];
        As[ak + 0][arow] = av.x;
        As[ak + 1][arow] = av.y;
        As[ak + 2][arow] = av.z;
        As[ak + 3][arow] = av.w;
        *(float4*)&Bs[brow][bn] =
            *(const float4*)&Xb[(size_t)(k0 + brow) * PP + n0 + bn];
        __syncthreads();
#pragma unroll
        for (int k = 0; k < 16; k++) {
            float4 a = *(const float4*)&As[k][ty << 2];
            float4 bq = *(const float4*)&Bs[k][tx << 2];
            acc[0][0] += a.x * bq.x; acc[0][1] += a.x * bq.y;
            acc[0][2] += a.x * bq.z; acc[0][3] += a.x * bq.w;
            acc[1][0] += a.y * bq.x; acc[1][1] += a.y * bq.y;
            acc[1][2] += a.y * bq.z; acc[1][3] += a.y * bq.w;
            acc[2][0] += a.z * bq.x; acc[2][1] += a.z * bq.y;
            acc[2][2] += a.z * bq.z; acc[2][3] += a.z * bq.w;
            acc[3][0] += a.w * bq.x; acc[3][1] += a.w * bq.y;
            acc[3][2] += a.w * bq.z; acc[3][3] += a.w * bq.w;
        }
        __syncthreads();
    }
#pragma unroll
    for (int i = 0; i < 4; i++) {
        int m = m0 + (ty << 2) + i;
        float bb = bias ? bias[m] : 0.f;
        float4 o = make_float4(acc[i][0] + bb, acc[i][1] + bb,
                               acc[i][2] + bb, acc[i][3] + bb);
        *(float4*)&Yb[(size_t)m * PP + n0 + (tx << 2)] = o;
    }
}

// ---------------- generic depthwise conv (KS x KS, dilation, pad) ----------------
__global__ void __launch_bounds__(256) dwconv(const float* __restrict__ X,
                                              const float* __restrict__ Wd,
                                              float* __restrict__ Y,
                                              int KS, int dil, int pad) {
    __shared__ float tile[PP];
    __shared__ float w[49];
    int bc = blockIdx.x;
    int c = bc & (CC - 1);
    const float* xp = X + (size_t)bc * PP;
    for (int p = threadIdx.x; p < PP; p += 256) tile[p] = xp[p];
    if (threadIdx.x < KS * KS) w[threadIdx.x] = Wd[c * KS * KS + threadIdx.x];
    __syncthreads();
    float* yp = Y + (size_t)bc * PP;
    for (int p = threadIdx.x; p < PP; p += 256) {
        int h = p >> 6, ww = p & 63;
        float s = 0.f;
        for (int kh = 0; kh < KS; kh++) {
            int hh = h + dil * kh - pad;
            if ((unsigned)hh >= (unsigned)HH) continue;
            for (int kw = 0; kw < KS; kw++) {
                int wc = ww + dil * kw - pad;
                if ((unsigned)wc >= (unsigned)WW) continue;
                s += tile[hh * WW + wc] * w[kh * KS + kw];
            }
        }
        yp[p] = s;
    }
}

// ---------------- c2a grouped conv (groups=32) + SimpleGate ----------------
__global__ void __launch_bounds__(256) c2a_gate(const float* __restrict__ X,
                                                const float* __restrict__ Wg,
                                                const float* __restrict__ bg,
                                                float* __restrict__ TG) {
    int b = blockIdx.x >> 4, j = blockIdx.x & 15;
    int p0 = blockIdx.y * 512;
    __shared__ float w1[72], w2[72];
    if (threadIdx.x < 72) w1[threadIdx.x] = Wg[j * 72 + threadIdx.x];
    else if (threadIdx.x < 144) w2[threadIdx.x - 72] = Wg[(16 + j) * 72 + threadIdx.x - 72];
    __syncthreads();
    float b1 = bg[j], b2 = bg[16 + j];
    const float* x1p = X + ((size_t)b * CC + j * 8) * PP;
    const float* x2p = X + ((size_t)b * CC + (16 + j) * 8) * PP;
    for (int p = p0 + threadIdx.x; p < p0 + 512; p += 256) {
        int h = p >> 6, wq = p & 63;
        float t1 = b1, t2 = b2;
        for (int ci = 0; ci < 8; ci++) {
            for (int kh = 0; kh < 3; kh++) {
                int hh = h + kh - 1;
                if ((unsigned)hh >= (unsigned)HH) continue;
                for (int kw = 0; kw < 3; kw++) {
                    int wc = wq + kw - 1;
                    if ((unsigned)wc >= (unsigned)WW) continue;
                    float xv1 = x1p[(size_t)ci * PP + hh * WW + wc];
                    float xv2 = x2p[(size_t)ci * PP + hh * WW + wc];
                    t1 += xv1 * w1[ci * 9 + kh * 3 + kw];
                    t2 += xv2 * w2[ci * 9 + kh * 3 + kw];
                }
            }
        }
        TG[((size_t)b * 16 + j) * PP + p] = t1 * t2;
    }
}

// ---------------- att = (conv1x1(tg,c2b)+b)*gamma + attlin ----------------
__global__ void __launch_bounds__(256) att_mix(const float* __restrict__ TG,
                                               const float* __restrict__ c2bw,
                                               const float* __restrict__ c2bb,
                                               const float* __restrict__ attg,
                                               const float* __restrict__ ATTLIN,
                                               float* __restrict__ ATT) {
    int n = blockIdx.x;
    int b = blockIdx.z;
    int p0 = blockIdx.y * 1024;
    float wr[16];
#pragma unroll
    for (int q = 0; q < 16; q++) wr[q] = c2bw[n * 16 + q];
    float bb = c2bb[n], gam = attg[n];
    const float* tgb = TG + (size_t)b * 16 * PP;
    size_t base = ((size_t)b * NSET + n) * PP;
    for (int p = p0 + threadIdx.x; p < p0 + 1024; p += 256) {
        float s = bb;
#pragma unroll
        for (int q = 0; q < 16; q++) s += tgb[(size_t)q * PP + p] * wr[q];
        ATT[base + p] = s * gam + ATTLIN[base + p];
    }
}

// ---------------- IKBA pass: fused [64pix x 48col x K128] GEMM + per-pixel matvec -----
// vertical=1: taps along H, no bias, OUT = xh
// vertical=0: taps along W on xh, +bias(b_cb), OUT = xw*ga1 + uf
__global__ void __launch_bounds__(256) ikba_pass(const float* __restrict__ ATT,
                                                 const float* __restrict__ wcb,
                                                 const float* __restrict__ bcb,
                                                 const float* __restrict__ ga1,
                                                 const float* __restrict__ SRC,
                                                 const float* __restrict__ UFR,
                                                 float* __restrict__ OUT,
                                                 int halfoff, int vertical) {
    extern __shared__ float sm[];
    float* As = sm;                  // 128*64 = 8192 floats  [k][pix]
    float* Bs = sm + 8192;           // 128*48 = 6144 floats  [k][col]
    float* bcs = sm + 8192 + 6144;   // 128*4 = 512 floats (horizontal only)
    float* Cs = As;                  // alias: [pix][49] (3136), after GEMM
    float* ufs = As + 3200;          // alias: [12][64] (768)

    int gr = blockIdx.x, h = blockIdx.y, b = blockIdx.z;
    int tid = threadIdx.x;

    size_t attBase = (size_t)b * NSET * PP + (size_t)h * WW;
    for (int l = tid; l < 2048; l += 256) {
        int k = l >> 4, m4 = (l & 15) << 2;
        *(float4*)&As[k * 64 + m4] =
            *(const float4*)&ATT[attBase + (size_t)k * PP + m4];
    }
    const float* wp = wcb + halfoff + gr * 48;
    for (int l = tid; l < 1536; l += 256) {
        int k = l / 12, j4 = (l % 12) << 2;
        *(float4*)&Bs[k * 48 + j4] = *(const float4*)&wp[(size_t)k * 6144 + j4];
    }
    if (!vertical) {
        for (int l = tid; l < 512; l += 256) {
            int k = l >> 2, i = l & 3;
            bcs[l] = bcb[k * CC + gr * CGC + i];
        }
    }
    __syncthreads();

    // GEMM: acc[i][t] = sum_k As[k][ty*4+i] * Bs[k][tx*3+t]
    int ty = tid >> 4, tx = tid & 15;
    float acc[4][3] = {};
    const float* ap = &As[ty * 4];
    const float* bp = &Bs[tx * 3];
#pragma unroll 4
    for (int k = 0; k < 128; k++) {
        float4 a = *(const float4*)&ap[k * 64];
        float b0 = bp[k * 48], b1 = bp[k * 48 + 1], b2 = bp[k * 48 + 2];
        acc[0][0] += a.x * b0; acc[0][1] += a.x * b1; acc[0][2] += a.x * b2;
        acc[1][0] += a.y * b0; acc[1][1] += a.y * b1; acc[1][2] += a.y * b2;
        acc[2][0] += a.z * b0; acc[2][1] += a.z * b1; acc[2][2] += a.z * b2;
        acc[3][0] += a.w * b0; acc[3][1] += a.w * b1; acc[3][2] += a.w * b2;
    }
    __syncthreads();

    int oi = tid >> 6, pix = tid & 63;
    float bv = 0.f;
    if (!vertical) {                 // uniform branch across block
        const float* av = &As[pix];
#pragma unroll 4
        for (int k = 0; k < 128; k++) bv += av[k * 64] * bcs[k * 4 + oi];
    }
    __syncthreads();                 // all As reads done before alias overwrite

    // write attk tile to smem (stride 49 to dodge bank conflicts)
#pragma unroll
    for (int i = 0; i < 4; i++)
#pragma unroll
        for (int t = 0; t < 3; t++)
            Cs[(ty * 4 + i) * 49 + tx * 3 + t] = acc[i][t];

    // load unfolded source values: ufs[j][pix], j = ci*3 + tap
    size_t srcBase = (size_t)(b * CC + gr * CGC) * PP;
    for (int l = tid; l < 768; l += 256) {
        int j = l >> 6, px = l & 63;
        int ci = j / 3, tap = j % 3;
        float v = 0.f;
        if (vertical) {
            int hh = h + tap - 1;
            if ((unsigned)hh < (unsigned)HH)
                v = SRC[srcBase + (size_t)ci * PP + hh * WW + px];
        } else {
            int wc = px + tap - 1;
            if ((unsigned)wc < (unsigned)WW)
                v = SRC[srcBase + (size_t)ci * PP + h * WW + wc];
        }
        ufs[j * 64 + px] = v;
    }
    __syncthreads();

    float s = vertical ? 0.f : bv;
    const float* cp = &Cs[pix * 49 + oi * 12];
#pragma unroll
    for (int j = 0; j < 12; j++) s += cp[j] * ufs[j * 64 + pix];

    size_t oidx = (size_t)(b * CC + gr * CGC + oi) * PP + (size_t)h * WW + pix;
    if (vertical) OUT[oidx] = s;
    else OUT[oidx] = s * ga1[gr * CGC + oi] + UFR[oidx];
}

// ---------------- elementwise z = x1*x2*lka*sca ----------------
__global__ void __launch_bounds__(256) ewmul(const float* __restrict__ A,
                                             const float* __restrict__ Bv,
                                             const float* __restrict__ Cv,
                                             const float* __restrict__ SCA,
                                             float* __restrict__ Z) {
    int i = blockIdx.x * 256 + threadIdx.x;
    if (i < BB * CC * PP) {
        int bc = i >> 12;
        Z[i] = A[i] * Bv[i] * Cv[i] * SCA[bc];
    }
}

// ---------------- launch ----------------
extern "C" void kernel_launch(void* const* d_in, const int* in_sizes, int n_in,
                              void* d_out, int out_size) {
    const float* x       = (const float*)d_in[0];
    const float* dw1_w   = (const float*)d_in[1];
    const float* dw2_w   = (const float*)d_in[2];
    const float* proj_w  = (const float*)d_in[3];
    const float* lka0_w  = (const float*)d_in[4];
    const float* lkas_w  = (const float*)d_in[5];
    const float* lka1_w  = (const float*)d_in[6];
    const float* lka1_b  = (const float*)d_in[7];
    const float* sca_w   = (const float*)d_in[8];
    const float* sca_b   = (const float*)d_in[9];
    const float* c1a_w   = (const float*)d_in[10];
    const float* c1b_w   = (const float*)d_in[11];
    const float* c2a_w   = (const float*)d_in[12];
    const float* c2a_b   = (const float*)d_in[13];
    const float* c2b_w   = (const float*)d_in[14];
    const float* c2b_b   = (const float*)d_in[15];
    const float* c211_w  = (const float*)d_in[16];
    const float* c211_b  = (const float*)d_in[17];
    const float* w_cb    = (const float*)d_in[18];
    const float* b_cb    = (const float*)d_in[19];
    const float* attgam  = (const float*)d_in[20];
    const float* ga1     = (const float*)d_in[21];
    float* out = (float*)d_out;

    float *meanb, *scab, *ydw1, *yc1a, *attlin, *x1b, *ufb, *l0, *l1, *lka,
          *tg, *att, *xh, *x2b, *zb;
    cudaGetSymbolAddress((void**)&meanb, g_mean);
    cudaGetSymbolAddress((void**)&scab, g_sca);
    cudaGetSymbolAddress((void**)&ydw1, g_ydw1);
    cudaGetSymbolAddress((void**)&yc1a, g_yc1a);
    cudaGetSymbolAddress((void**)&attlin, g_attlin);
    cudaGetSymbolAddress((void**)&x1b, g_x1);
    cudaGetSymbolAddress((void**)&ufb, g_uf);
    cudaGetSymbolAddress((void**)&l0, g_l0);
    cudaGetSymbolAddress((void**)&l1, g_l1);
    cudaGetSymbolAddress((void**)&lka, g_lka);
    cudaGetSymbolAddress((void**)&tg, g_tg);
    cudaGetSymbolAddress((void**)&att, g_att);
    cudaGetSymbolAddress((void**)&xh, g_xh);
    cudaGetSymbolAddress((void**)&x2b, g_x2);
    cudaGetSymbolAddress((void**)&zb, g_z);

    // channel-attention branch
    meankern<<<BB * CC, 256>>>(x, meanb);
    scakern<<<BB, 256>>>(meanb, sca_w, sca_b, scab);

    // 1x1 convs from x
    gemm1x1<<<dim3(64, 4, BB), 256>>>(dw1_w, x, nullptr, ydw1, 256, 256);
    gemm1x1<<<dim3(64, 4, BB), 256>>>(c1a_w, x, nullptr, yc1a, 256, 256);
    gemm1x1<<<dim3(64, 2, BB), 256>>>(c211_w, x, c211_b, attlin, 128, 256);

    // depthwise chains
    dwconv<<<BB * CC, 256>>>(ydw1, dw2_w, x1b, 3, 1, 1);
    dwconv<<<BB * CC, 256>>>(yc1a, c1b_w, ufb, 3, 1, 1);
    dwconv<<<BB * CC, 256>>>(x, lka0_w, l0, 5, 1, 2);
    dwconv<<<BB * CC, 256>>>(l0, lkas_w, l1, 7, 3, 9);
    gemm1x1<<<dim3(64, 4, BB), 256>>>(lka1_w, l1, lka1_b, lka, 256, 256);

    // attention map
    c2a_gate<<<dim3(BB * 16, 8), 256>>>(x, c2a_w, c2a_b, tg);
    att_mix<<<dim3(NSET, 4, BB), 256>>>(tg, c2b_w, c2b_b, attgam, attlin, att);

    // IKBA (fused GEMM + dynamic conv)
    cudaFuncSetAttribute(ikba_pass, cudaFuncAttributeMaxDynamicSharedMemorySize, 61440);
    size_t shmem = (8192 + 6144 + 512) * sizeof(float);
    ikba_pass<<<dim3(GG, HH, BB), 256, shmem>>>(att, w_cb, b_cb, ga1, ufb,
                                                nullptr, xh, 0, 1);
    ikba_pass<<<dim3(GG, HH, BB), 256, shmem>>>(att, w_cb, b_cb, ga1, xh,
                                                ufb, x2b, 3072, 0);

    // final merge + projection
    ewmul<<<(BB * CC * PP + 255) / 256, 256>>>(x1b, x2b, lka, scab, zb);
    gemm1x1<<<dim3(64, 4, BB), 256>>>(proj_w, zb, nullptr, out, 256, 256);
}

// round 2
// speedup vs baseline: 1.0580x; 1.0580x over previous
#include <cuda_runtime.h>
#include <cuda_bf16.h>
#include <cstddef>

// Problem constants
#define BB 2
#define CC 256
#define HH 64
#define WW 64
#define PP 4096          // H*W
#define NSET 128
#define GG 64            // groups
#define CGC 4            // channels per group
#define KTAP 3

// ---------------- scratch (device globals; no allocs allowed) ----------------
__device__ float g_mean[BB * CC];
__device__ float g_sca[BB * CC];
__device__ float g_ydw1[BB * CC * PP];
__device__ float g_yc1a[BB * CC * PP];
__device__ float g_attlin[BB * NSET * PP];
__device__ float g_x1[BB * CC * PP];
__device__ float g_uf[BB * CC * PP];
__device__ float g_l0[BB * CC * PP];
__device__ float g_l1[BB * CC * PP];
__device__ float g_lka[BB * CC * PP];
__device__ float g_tg[BB * 16 * PP];
__device__ float g_att[BB * NSET * PP];
__device__ float g_xh[BB * CC * PP];
__device__ float g_x2[BB * CC * PP];
__device__ float g_z[BB * CC * PP];

// ---------------- mean over H,W per (b,c) ----------------
__global__ void __launch_bounds__(256) meankern(const float* __restrict__ X,
                                                float* __restrict__ M) {
    int bc = blockIdx.x;
    const float4* xp = (const float4*)(X + (size_t)bc * PP);
    float s = 0.f;
    for (int p = threadIdx.x; p < PP / 4; p += 256) {
        float4 v = xp[p];
        s += v.x + v.y + v.z + v.w;
    }
    __shared__ float red[256];
    red[threadIdx.x] = s;
    __syncthreads();
    for (int st = 128; st > 0; st >>= 1) {
        if (threadIdx.x < st) red[threadIdx.x] += red[threadIdx.x + st];
        __syncthreads();
    }
    if (threadIdx.x == 0) M[bc] = red[0] * (1.f / PP);
}

// ---------------- sca = 1x1 conv on the mean vector ----------------
__global__ void __launch_bounds__(256) scakern(const float* __restrict__ M,
                                               const float* __restrict__ Wsca,
                                               const float* __restrict__ Bsca,
                                               float* __restrict__ SCA) {
    int b = blockIdx.x;
    int o = threadIdx.x;
    __shared__ float m[CC];
    m[o] = M[b * CC + o];
    __syncthreads();
    float s = Bsca[o];
    const float* wr = Wsca + (size_t)o * CC;
    for (int c = 0; c < CC; c++) s += wr[c] * m[c];
    SCA[b * CC + o] = s;
}

// ---------------- 1x1 conv GEMM: tile 64M x 128N, thread 4x8 ----------------
__global__ void __launch_bounds__(256) gemm1x1(const float* __restrict__ Wm,
                                               const float* __restrict__ X,
                                               const float* __restrict__ bias,
                                               float* __restrict__ Y,
                                               int M, int K) {
    __shared__ float As[16][68];   // [k][m]
    __shared__ float Bs[16][128];  // [k][n]
    int b = blockIdx.z;
    int m0 = blockIdx.y << 6, n0 = blockIdx.x << 7;
    const float* Xb = X + (size_t)b * K * PP;
    float* Yb = Y + (size_t)b * M * PP;
    int tid = threadIdx.x;
    int tx = tid & 15, ty = tid >> 4;
    int arow = tid >> 2, ak = (tid & 3) << 2;
    int brow = tid >> 4, bn = (tid & 15) << 3;
    float acc[4][8] = {};
    for (int k0 = 0; k0 < K; k0 += 16) {
        float4 av = *(const float4*)&Wm[(size_t)(m0 + arow) * K + k0 + ak];
        As[ak + 0][arow] = av.x;
        As[ak + 1][arow] = av.y;
        As[ak + 2][arow] = av.z;
        As[ak + 3][arow] = av.w;
        const float* xr = &Xb[(size_t)(k0 + brow) * PP + n0 + bn];
        *(float4*)&Bs[brow][bn] = *(const float4*)xr;
        *(float4*)&Bs[brow][bn + 4] = *(const float4*)(xr + 4);
        __syncthreads();
#pragma unroll
        for (int k = 0; k < 16; k++) {
            float4 a = *(const float4*)&As[k][ty << 2];
            float4 b0 = *(const float4*)&Bs[k][tx << 3];
            float4 b1 = *(const float4*)&Bs[k][(tx << 3) + 4];
            acc[0][0] += a.x * b0.x; acc[0][1] += a.x * b0.y;
            acc[0][2] += a.x * b0.z; acc[0][3] += a.x * b0.w;
            acc[0][4] += a.x * b1.x; acc[0][5] += a.x * b1.y;
            acc[0][6] += a.x * b1.z; acc[0][7] += a.x * b1.w;
            acc[1][0] += a.y * b0.x; acc[1][1] += a.y * b0.y;
            acc[1][2] += a.y * b0.z; acc[1][3] += a.y * b0.w;
            acc[1][4] += a.y * b1.x; acc[1][5] += a.y * b1.y;
            acc[1][6] += a.y * b1.z; acc[1][7] += a.y * b1.w;
            acc[2][0] += a.z * b0.x; acc[2][1] += a.z * b0.y;
            acc[2][2] += a.z * b0.z; acc[2][3] += a.z * b0.w;
            acc[2][4] += a.z * b1.x; acc[2][5] += a.z * b1.y;
            acc[2][6] += a.z * b1.z; acc[2][7] += a.z * b1.w;
            acc[3][0] += a.w * b0.x; acc[3][1] += a.w * b0.y;
            acc[3][2] += a.w * b0.z; acc[3][3] += a.w * b0.w;
            acc[3][4] += a.w * b1.x; acc[3][5] += a.w * b1.y;
            acc[3][6] += a.w * b1.z; acc[3][7] += a.w * b1.w;
        }
        __syncthreads();
    }
#pragma unroll
    for (int i = 0; i < 4; i++) {
        int m = m0 + (ty << 2) + i;
        float bb = bias ? bias[m] : 0.f;
        float* yr = &Yb[(size_t)m * PP + n0 + (tx << 3)];
        float4 o0 = make_float4(acc[i][0] + bb, acc[i][1] + bb,
                                acc[i][2] + bb, acc[i][3] + bb);
        float4 o1 = make_float4(acc[i][4] + bb, acc[i][5] + bb,
                                acc[i][6] + bb, acc[i][7] + bb);
        *(float4*)yr = o0;
        *(float4*)(yr + 4) = o1;
    }
}

// ---------------- depthwise conv, compile-time KS/dil/pad ----------------
template <int KS, int DIL, int PAD>
__global__ void __launch_bounds__(256) dwconv(const float* __restrict__ X,
                                              const float* __restrict__ Wd,
                                              float* __restrict__ Y) {
    __shared__ float tile[PP];
    __shared__ float w[KS * KS];
    int bc = blockIdx.x;
    int c = bc & (CC - 1);
    const float4* xp = (const float4*)(X + (size_t)bc * PP);
    for (int p = threadIdx.x; p < PP / 4; p += 256)
        ((float4*)tile)[p] = xp[p];
    if (threadIdx.x < KS * KS) w[threadIdx.x] = Wd[c * KS * KS + threadIdx.x];
    __syncthreads();
    float* yp = Y + (size_t)bc * PP;
    for (int p = threadIdx.x; p < PP; p += 256) {
        int h = p >> 6, ww = p & 63;
        float s = 0.f;
#pragma unroll
        for (int kh = 0; kh < KS; kh++) {
            int hh = h + DIL * kh - PAD;
            if ((unsigned)hh >= (unsigned)HH) continue;
#pragma unroll
            for (int kw = 0; kw < KS; kw++) {
                int wc = ww + DIL * kw - PAD;
                if ((unsigned)wc >= (unsigned)WW) continue;
                s += tile[hh * WW + wc] * w[kh * KS + kw];
            }
        }
        yp[p] = s;
    }
}

// ---------------- c2a grouped conv (groups=32) + SimpleGate ----------------
__global__ void __launch_bounds__(256) c2a_gate(const float* __restrict__ X,
                                                const float* __restrict__ Wg,
                                                const float* __restrict__ bg,
                                                float* __restrict__ TG) {
    int b = blockIdx.x >> 4, j = blockIdx.x & 15;
    int p0 = blockIdx.y * 512;
    __shared__ float w1[72], w2[72];
    if (threadIdx.x < 72) w1[threadIdx.x] = Wg[j * 72 + threadIdx.x];
    else if (threadIdx.x < 144) w2[threadIdx.x - 72] = Wg[(16 + j) * 72 + threadIdx.x - 72];
    __syncthreads();
    float b1 = bg[j], b2 = bg[16 + j];
    const float* x1p = X + ((size_t)b * CC + j * 8) * PP;
    const float* x2p = X + ((size_t)b * CC + (16 + j) * 8) * PP;
    for (int p = p0 + threadIdx.x; p < p0 + 512; p += 256) {
        int h = p >> 6, wq = p & 63;
        float t1 = b1, t2 = b2;
        for (int ci = 0; ci < 8; ci++) {
#pragma unroll
            for (int kh = 0; kh < 3; kh++) {
                int hh = h + kh - 1;
                if ((unsigned)hh >= (unsigned)HH) continue;
#pragma unroll
                for (int kw = 0; kw < 3; kw++) {
                    int wc = wq + kw - 1;
                    if ((unsigned)wc >= (unsigned)WW) continue;
                    float xv1 = x1p[(size_t)ci * PP + hh * WW + wc];
                    float xv2 = x2p[(size_t)ci * PP + hh * WW + wc];
                    t1 += xv1 * w1[ci * 9 + kh * 3 + kw];
                    t2 += xv2 * w2[ci * 9 + kh * 3 + kw];
                }
            }
        }
        TG[((size_t)b * 16 + j) * PP + p] = t1 * t2;
    }
}

// ---------------- att = (conv1x1(tg,c2b)+b)*gamma + attlin ----------------
__global__ void __launch_bounds__(256) att_mix(const float* __restrict__ TG,
                                               const float* __restrict__ c2bw,
                                               const float* __restrict__ c2bb,
                                               const float* __restrict__ attg,
                                               const float* __restrict__ ATTLIN,
                                               float* __restrict__ ATT) {
    int n = blockIdx.x;
    int b = blockIdx.z;
    int p0 = blockIdx.y * 1024;
    float wr[16];
#pragma unroll
    for (int q = 0; q < 16; q++) wr[q] = c2bw[n * 16 + q];
    float bb = c2bb[n], gam = attg[n];
    const float* tgb = TG + (size_t)b * 16 * PP;
    size_t base = ((size_t)b * NSET + n) * PP;
    for (int p = p0 + threadIdx.x; p < p0 + 1024; p += 256) {
        float s = bb;
#pragma unroll
        for (int q = 0; q < 16; q++) s += tgb[(size_t)q * PP + p] * wr[q];
        ATT[base + p] = s * gam + ATTLIN[base + p];
    }
}

// ---------------- IKBA pass: 2 H-rows per block, fused GEMM + dyn conv -----
// Per block: 128 pixels x 48 cols x K=128 GEMM, then per-pixel 4x12 matvec.
// vertical=1: taps along H, no bias, OUT = xh
// vertical=0: taps along W on xh, +bias(b_cb), OUT = xw*ga1 + uf
__global__ void __launch_bounds__(256) ikba_pass(const float* __restrict__ ATT,
                                                 const float* __restrict__ wcb,
                                                 const float* __restrict__ bcb,
                                                 const float* __restrict__ ga1,
                                                 const float* __restrict__ SRC,
                                                 const float* __restrict__ UFR,
                                                 float* __restrict__ OUT,
                                                 int halfoff, int vertical) {
    extern __shared__ float sm[];
    float* As = sm;                   // 128k * 128pix = 16384 floats
    float* Bs = sm + 16384;           // 128k * 48col  =  6144 floats
    float* bcs = sm + 16384 + 6144;   // 128k * 4ch    =   512 floats
    float* Cs = As;                   // alias: [pix][49] = 6272
    float* ufs = As + 6272;           // alias: [12][128] = 1536

    int gr = blockIdx.x, h2 = blockIdx.y, b = blockIdx.z;
    int tid = threadIdx.x;

    // load attention tile: 128 k x 128 contiguous pixels (rows 2*h2, 2*h2+1)
    size_t attBase = (size_t)b * NSET * PP + (size_t)h2 * 128;
    for (int l = tid; l < 4096; l += 256) {
        int k = l >> 5, m4 = (l & 31) << 2;
        *(float4*)&As[k * 128 + m4] =
            *(const float4*)&ATT[attBase + (size_t)k * PP + m4];
    }
    const float* wp = wcb + halfoff + gr * 48;
    for (int l = tid; l < 1536; l += 256) {
        int k = l / 12, j4 = (l % 12) << 2;
        *(float4*)&Bs[k * 48 + j4] = *(const float4*)&wp[(size_t)k * 6144 + j4];
    }
    if (!vertical) {
        for (int l = tid; l < 512; l += 256) {
            int k = l >> 2, i = l & 3;
            bcs[l] = bcb[k * CC + gr * CGC + i];
        }
    }
    __syncthreads();

    // GEMM: acc[i][t] = sum_k As[k][ty*4+i] * Bs[k][tx*6+t]
    int ty = tid >> 3, tx = tid & 7;
    float acc[4][6] = {};
    const float* ap = &As[ty * 4];
    const float* bp = &Bs[tx * 6];
#pragma unroll 2
    for (int k = 0; k < 128; k++) {
        float4 a = *(const float4*)&ap[k * 128];
        float2 b01 = *(const float2*)&bp[k * 48];
        float2 b23 = *(const float2*)&bp[k * 48 + 2];
        float2 b45 = *(const float2*)&bp[k * 48 + 4];
        acc[0][0] += a.x * b01.x; acc[0][1] += a.x * b01.y;
        acc[0][2] += a.x * b23.x; acc[0][3] += a.x * b23.y;
        acc[0][4] += a.x * b45.x; acc[0][5] += a.x * b45.y;
        acc[1][0] += a.y * b01.x; acc[1][1] += a.y * b01.y;
        acc[1][2] += a.y * b23.x; acc[1][3] += a.y * b23.y;
        acc[1][4] += a.y * b45.x; acc[1][5] += a.y * b45.y;
        acc[2][0] += a.z * b01.x; acc[2][1] += a.z * b01.y;
        acc[2][2] += a.z * b23.x; acc[2][3] += a.z * b23.y;
        acc[2][4] += a.z * b45.x; acc[2][5] += a.z * b45.y;
        acc[3][0] += a.w * b01.x; acc[3][1] += a.w * b01.y;
        acc[3][2] += a.w * b23.x; acc[3][3] += a.w * b23.y;
        acc[3][4] += a.w * b45.x; acc[3][5] += a.w * b45.y;
    }
    __syncthreads();

    // bias matvec (horizontal pass only): each thread handles 2 of 4 channels
    int pix = tid & 127, oih = tid >> 7;   // oih in {0,1}; channels oih, oih+2
    float bv0 = 0.f, bv1 = 0.f;
    if (!vertical) {
        const float* av = &As[pix];
#pragma unroll 4
        for (int k = 0; k < 128; k++) {
            float a = av[k * 128];
            bv0 += a * bcs[k * 4 + oih];
            bv1 += a * bcs[k * 4 + oih + 2];
        }
    }
    __syncthreads();   // all As reads done before alias overwrite

    // write attk tile into smem (row stride 49)
#pragma unroll
    for (int i = 0; i < 4; i++)
#pragma unroll
        for (int t = 0; t < 6; t++)
            Cs[(ty * 4 + i) * 49 + tx * 6 + t] = acc[i][t];

    // unfolded source: ufs[j][pix], j = ci*3 + tap
    size_t srcBase = (size_t)(b * CC + gr * CGC) * PP;
    for (int l = tid; l < 1536; l += 256) {
        int j = l >> 7, px = l & 127;
        int ci = j / 3, tap = j % 3;
        float v = 0.f;
        if (vertical) {
            int hh = h2 * 2 + (px >> 6) + tap - 1;
            if ((unsigned)hh < (unsigned)HH)
                v = SRC[srcBase + (size_t)ci * PP + hh * WW + (px & 63)];
        } else {
            int wc = (px & 63) + tap - 1;
            int h = h2 * 2 + (px >> 6);
            if ((unsigned)wc < (unsigned)WW)
                v = SRC[srcBase + (size_t)ci * PP + h * WW + wc];
        }
        ufs[j * 128 + px] = v;
    }
    __syncthreads();

#pragma unroll
    for (int q = 0; q < 2; q++) {
        int oi = oih + q * 2;
        float s = vertical ? 0.f : (q == 0 ? bv0 : bv1);
        const float* cp = &Cs[pix * 49 + oi * 12];
#pragma unroll
        for (int j = 0; j < 12; j++) s += cp[j] * ufs[j * 128 + pix];
        size_t oidx = (size_t)(b * CC + gr * CGC + oi) * PP + (size_t)h2 * 128 + pix;
        if (vertical) OUT[oidx] = s;
        else OUT[oidx] = s * ga1[gr * CGC + oi] + UFR[oidx];
    }
}

// ---------------- elementwise z = x1*x2*lka*sca ----------------
__global__ void __launch_bounds__(256) ewmul(const float* __restrict__ A,
                                             const float* __restrict__ Bv,
                                             const float* __restrict__ Cv,
                                             const float* __restrict__ SCA,
                                             float* __restrict__ Z) {
    int i = blockIdx.x * 256 + threadIdx.x;
    if (i < BB * CC * PP) {
        int bc = i >> 12;
        Z[i] = A[i] * Bv[i] * Cv[i] * SCA[bc];
    }
}

// ---------------- launch ----------------
extern "C" void kernel_launch(void* const* d_in, const int* in_sizes, int n_in,
                              void* d_out, int out_size) {
    const float* x       = (const float*)d_in[0];
    const float* dw1_w   = (const float*)d_in[1];
    const float* dw2_w   = (const float*)d_in[2];
    const float* proj_w  = (const float*)d_in[3];
    const float* lka0_w  = (const float*)d_in[4];
    const float* lkas_w  = (const float*)d_in[5];
    const float* lka1_w  = (const float*)d_in[6];
    const float* lka1_b  = (const float*)d_in[7];
    const float* sca_w   = (const float*)d_in[8];
    const float* sca_b   = (const float*)d_in[9];
    const float* c1a_w   = (const float*)d_in[10];
    const float* c1b_w   = (const float*)d_in[11];
    const float* c2a_w   = (const float*)d_in[12];
    const float* c2a_b   = (const float*)d_in[13];
    const float* c2b_w   = (const float*)d_in[14];
    const float* c2b_b   = (const float*)d_in[15];
    const float* c211_w  = (const float*)d_in[16];
    const float* c211_b  = (const float*)d_in[17];
    const float* w_cb    = (const float*)d_in[18];
    const float* b_cb    = (const float*)d_in[19];
    const float* attgam  = (const float*)d_in[20];
    const float* ga1     = (const float*)d_in[21];
    float* out = (float*)d_out;

    float *meanb, *scab, *ydw1, *yc1a, *attlin, *x1b, *ufb, *l0, *l1, *lka,
          *tg, *att, *xh, *x2b, *zb;
    cudaGetSymbolAddress((void**)&meanb, g_mean);
    cudaGetSymbolAddress((void**)&scab, g_sca);
    cudaGetSymbolAddress((void**)&ydw1, g_ydw1);
    cudaGetSymbolAddress((void**)&yc1a, g_yc1a);
    cudaGetSymbolAddress((void**)&attlin, g_attlin);
    cudaGetSymbolAddress((void**)&x1b, g_x1);
    cudaGetSymbolAddress((void**)&ufb, g_uf);
    cudaGetSymbolAddress((void**)&l0, g_l0);
    cudaGetSymbolAddress((void**)&l1, g_l1);
    cudaGetSymbolAddress((void**)&lka, g_lka);
    cudaGetSymbolAddress((void**)&tg, g_tg);
    cudaGetSymbolAddress((void**)&att, g_att);
    cudaGetSymbolAddress((void**)&xh, g_xh);
    cudaGetSymbolAddress((void**)&x2b, g_x2);
    cudaGetSymbolAddress((void**)&zb, g_z);

    // channel-attention branch
    meankern<<<BB * CC, 256>>>(x, meanb);
    scakern<<<BB, 256>>>(meanb, sca_w, sca_b, scab);

    // 1x1 convs from x
    gemm1x1<<<dim3(32, 4, BB), 256>>>(dw1_w, x, nullptr, ydw1, 256, 256);
    gemm1x1<<<dim3(32, 4, BB), 256>>>(c1a_w, x, nullptr, yc1a, 256, 256);
    gemm1x1<<<dim3(32, 2, BB), 256>>>(c211_w, x, c211_b, attlin, 128, 256);

    // depthwise chains
    dwconv<3, 1, 1><<<BB * CC, 256>>>(ydw1, dw2_w, x1b);
    dwconv<3, 1, 1><<<BB * CC, 256>>>(yc1a, c1b_w, ufb);
    dwconv<5, 1, 2><<<BB * CC, 256>>>(x, lka0_w, l0);
    dwconv<7, 3, 9><<<BB * CC, 256>>>(l0, lkas_w, l1);
    gemm1x1<<<dim3(32, 4, BB), 256>>>(lka1_w, l1, lka1_b, lka, 256, 256);

    // attention map
    c2a_gate<<<dim3(BB * 16, 8), 256>>>(x, c2a_w, c2a_b, tg);
    att_mix<<<dim3(NSET, 4, BB), 256>>>(tg, c2b_w, c2b_b, attgam, attlin, att);

    // IKBA (fused GEMM + dynamic conv), 2 H-rows per block
    cudaFuncSetAttribute(ikba_pass, cudaFuncAttributeMaxDynamicSharedMemorySize,
                         (16384 + 6144 + 512) * 4);
    size_t shmem = (16384 + 6144 + 512) * sizeof(float);
    ikba_pass<<<dim3(GG, 32, BB), 256, shmem>>>(att, w_cb, b_cb, ga1, ufb,
                                                nullptr, xh, 0, 1);
    ikba_pass<<<dim3(GG, 32, BB), 256, shmem>>>(att, w_cb, b_cb, ga1, xh,
                                                ufb, x2b, 3072, 0);

    // final merge + projection
    ewmul<<<(BB * CC * PP + 255) / 256, 256>>>(x1b, x2b, lka, scab, zb);
    gemm1x1<<<dim3(32, 4, BB), 256>>>(proj_w, zb, nullptr, out, 256, 256);
}

// round 4
// speedup vs baseline: 1.2260x; 1.1587x over previous
#include <cuda_runtime.h>
#include <cuda_bf16.h>
#include <cstdint>
#include <cstddef>

// Problem constants
#define BB 2
#define CC 256
#define HH 64
#define WW 64
#define PP 4096          // H*W
#define NSET 128
#define GG 64            // groups
#define CGC 4            // channels per group

// ---------------- scratch (device globals; no allocs allowed) ----------------
__device__ float g_mean[BB * CC];
__device__ float g_sca[BB * CC];
__device__ float g_ydw1[BB * CC * PP];
__device__ float g_yc1a[BB * CC * PP];
__device__ float g_attlin[BB * NSET * PP];
__device__ float g_x1[BB * CC * PP];
__device__ float g_uf[BB * CC * PP];
__device__ float g_l0[BB * CC * PP];
__device__ float g_l1[BB * CC * PP];
__device__ float g_tg[BB * 16 * PP];
__device__ float g_att[BB * NSET * PP];
__device__ float g_xh[BB * CC * PP];
__device__ float g_x2[BB * CC * PP];
__device__ float g_z[BB * CC * PP];

__device__ __forceinline__ uint32_t f2tf(float f) {
    uint32_t r;
    asm("cvt.rna.tf32.f32 %0, %1;" : "=r"(r) : "f"(f));
    return r;
}

// ---------------- mean over H,W per (b,c) ----------------
__global__ void __launch_bounds__(256) meankern(const float* __restrict__ X,
                                                float* __restrict__ M) {
    int bc = blockIdx.x;
    const float4* xp = (const float4*)(X + (size_t)bc * PP);
    float s = 0.f;
    for (int p = threadIdx.x; p < PP / 4; p += 256) {
        float4 v = xp[p];
        s += v.x + v.y + v.z + v.w;
    }
    __shared__ float red[256];
    red[threadIdx.x] = s;
    __syncthreads();
    for (int st = 128; st > 0; st >>= 1) {
        if (threadIdx.x < st) red[threadIdx.x] += red[threadIdx.x + st];
        __syncthreads();
    }
    if (threadIdx.x == 0) M[bc] = red[0] * (1.f / PP);
}

// ---------------- sca = 1x1 conv on the mean vector ----------------
__global__ void __launch_bounds__(256) scakern(const float* __restrict__ M,
                                               const float* __restrict__ Wsca,
                                               const float* __restrict__ Bsca,
                                               float* __restrict__ SCA) {
    int b = blockIdx.x;
    int o = threadIdx.x;
    __shared__ float m[CC];
    m[o] = M[b * CC + o];
    __syncthreads();
    float s = Bsca[o];
    const float* wr = Wsca + (size_t)o * CC;
    for (int c = 0; c < CC; c++) s += wr[c] * m[c];
    SCA[b * CC + o] = s;
}

// ---------------- core 64x64 SIMT GEMM body (device inline) ----------------
__device__ __forceinline__ void gemm_core(const float* __restrict__ Wm,
                                          const float* __restrict__ Xb,
                                          int m0, int n0, int K,
                                          float (&acc)[4][4]) {
    __shared__ float As[16][68];
    __shared__ float Bs[16][64];
    int tid = threadIdx.x;
    int tx = tid & 15, ty = tid >> 4;
    int arow = tid >> 2, ak = (tid & 3) << 2;
    int brow = tid >> 4, bn = (tid & 15) << 2;
    for (int k0 = 0; k0 < K; k0 += 16) {
        float4 av = *(const float4*)&Wm[(size_t)(m0 + arow) * K + k0 + ak];
        As[ak + 0][arow] = av.x;
        As[ak + 1][arow] = av.y;
        As[ak + 2][arow] = av.z;
        As[ak + 3][arow] = av.w;
        *(float4*)&Bs[brow][bn] =
            *(const float4*)&Xb[(size_t)(k0 + brow) * PP + n0 + bn];
        __syncthreads();
#pragma unroll
        for (int k = 0; k < 16; k++) {
            float4 a = *(const float4*)&As[k][ty << 2];
            float4 bq = *(const float4*)&Bs[k][tx << 2];
            acc[0][0] += a.x * bq.x; acc[0][1] += a.x * bq.y;
            acc[0][2] += a.x * bq.z; acc[0][3] += a.x * bq.w;
            acc[1][0] += a.y * bq.x; acc[1][1] += a.y * bq.y;
            acc[1][2] += a.y * bq.z; acc[1][3] += a.y * bq.w;
            acc[2][0] += a.z * bq.x; acc[2][1] += a.z * bq.y;
            acc[2][2] += a.z * bq.z; acc[2][3] += a.z * bq.w;
            acc[3][0] += a.w * bq.x; acc[3][1] += a.w * bq.y;
            acc[3][2] += a.w * bq.z; acc[3][3] += a.w * bq.w;
        }
        __syncthreads();
    }
}

// ---------------- plain 1x1 GEMM (proj) ----------------
__global__ void __launch_bounds__(256) gemm1x1(const float* __restrict__ Wm,
                                               const float* __restrict__ X,
                                               const float* __restrict__ bias,
                                               float* __restrict__ Y,
                                               int M, int K) {
    int b = blockIdx.z;
    int m0 = blockIdx.y << 6, n0 = blockIdx.x << 6;
    float acc[4][4] = {};
    gemm_core(Wm, X + (size_t)b * K * PP, m0, n0, K, acc);
    int tid = threadIdx.x, tx = tid & 15, ty = tid >> 4;
    float* Yb = Y + (size_t)b * M * PP;
#pragma unroll
    for (int i = 0; i < 4; i++) {
        int m = m0 + (ty << 2) + i;
        float bb = bias ? bias[m] : 0.f;
        float4 o = make_float4(acc[i][0] + bb, acc[i][1] + bb,
                               acc[i][2] + bb, acc[i][3] + bb);
        *(float4*)&Yb[(size_t)m * PP + n0 + (tx << 2)] = o;
    }
}

// ---------------- batched 3-way 1x1 GEMM (dw1 | c1a | c211) ----------------
__global__ void __launch_bounds__(256) gemm3(const float* __restrict__ W0,
                                             const float* __restrict__ W1,
                                             const float* __restrict__ W2,
                                             const float* __restrict__ b2,
                                             const float* __restrict__ X,
                                             float* __restrict__ Y0,
                                             float* __restrict__ Y1,
                                             float* __restrict__ Y2) {
    int b = blockIdx.z;
    int my = blockIdx.y, n0 = blockIdx.x << 6;
    const float* Wm;
    float* Y;
    const float* bias = nullptr;
    int m0, Msel;
    if (my < 4)      { Wm = W0; Y = Y0; m0 = my << 6; Msel = 256; }
    else if (my < 8) { Wm = W1; Y = Y1; m0 = (my - 4) << 6; Msel = 256; }
    else             { Wm = W2; Y = Y2; m0 = (my - 8) << 6; Msel = 128; bias = b2; }
    float acc[4][4] = {};
    gemm_core(Wm, X + (size_t)b * CC * PP, m0, n0, CC, acc);
    int tid = threadIdx.x, tx = tid & 15, ty = tid >> 4;
    float* Yb = Y + (size_t)b * Msel * PP;
#pragma unroll
    for (int i = 0; i < 4; i++) {
        int m = m0 + (ty << 2) + i;
        float bb = bias ? bias[m] : 0.f;
        float4 o = make_float4(acc[i][0] + bb, acc[i][1] + bb,
                               acc[i][2] + bb, acc[i][3] + bb);
        *(float4*)&Yb[(size_t)m * PP + n0 + (tx << 2)] = o;
    }
}

// ---------------- lka1 GEMM with fused z = lka*x1*x2*sca epilogue ----------------
__global__ void __launch_bounds__(256) gemm_lka_ew(const float* __restrict__ Wm,
                                                   const float* __restrict__ X,
                                                   const float* __restrict__ bias,
                                                   const float* __restrict__ X1,
                                                   const float* __restrict__ X2,
                                                   const float* __restrict__ SCA,
                                                   float* __restrict__ Z) {
    int b = blockIdx.z;
    int m0 = blockIdx.y << 6, n0 = blockIdx.x << 6;
    float acc[4][4] = {};
    gemm_core(Wm, X + (size_t)b * CC * PP, m0, n0, CC, acc);
    int tid = threadIdx.x, tx = tid & 15, ty = tid >> 4;
    size_t bbase = (size_t)b * CC * PP;
#pragma unroll
    for (int i = 0; i < 4; i++) {
        int m = m0 + (ty << 2) + i;
        float bb = bias[m];
        float sc = SCA[b * CC + m];
        size_t idx = bbase + (size_t)m * PP + n0 + (tx << 2);
        float4 v1 = *(const float4*)&X1[idx];
        float4 v2 = *(const float4*)&X2[idx];
        float4 o = make_float4((acc[i][0] + bb) * v1.x * v2.x * sc,
                               (acc[i][1] + bb) * v1.y * v2.y * sc,
                               (acc[i][2] + bb) * v1.z * v2.z * sc,
                               (acc[i][3] + bb) * v1.w * v2.w * sc);
        *(float4*)&Z[idx] = o;
    }
}

// ---------------- depthwise conv, compile-time KS/dil/pad ----------------
template <int KS, int DIL, int PAD>
__global__ void __launch_bounds__(256) dwconv(const float* __restrict__ X,
                                              const float* __restrict__ Wd,
                                              float* __restrict__ Y) {
    __shared__ float tile[PP];
    __shared__ float w[KS * KS];
    int bc = blockIdx.x;
    int c = bc & (CC - 1);
    const float4* xp = (const float4*)(X + (size_t)bc * PP);
    for (int p = threadIdx.x; p < PP / 4; p += 256)
        ((float4*)tile)[p] = xp[p];
    if (threadIdx.x < KS * KS) w[threadIdx.x] = Wd[c * KS * KS + threadIdx.x];
    __syncthreads();
    float* yp = Y + (size_t)bc * PP;
    for (int p = threadIdx.x; p < PP; p += 256) {
        int h = p >> 6, ww = p & 63;
        float s = 0.f;
#pragma unroll
        for (int kh = 0; kh < KS; kh++) {
            int hh = h + DIL * kh - PAD;
            if ((unsigned)hh >= (unsigned)HH) continue;
#pragma unroll
            for (int kw = 0; kw < KS; kw++) {
                int wc = ww + DIL * kw - PAD;
                if ((unsigned)wc >= (unsigned)WW) continue;
                s += tile[hh * WW + wc] * w[kh * KS + kw];
            }
        }
        yp[p] = s;
    }
}

// ---------------- c2a grouped conv (groups=32) + SimpleGate ----------------
__global__ void __launch_bounds__(256) c2a_gate(const float* __restrict__ X,
                                                const float* __restrict__ Wg,
                                                const float* __restrict__ bg,
                                                float* __restrict__ TG) {
    int b = blockIdx.x >> 4, j = blockIdx.x & 15;
    int p0 = blockIdx.y * 512;
    __shared__ float w1[72], w2[72];
    if (threadIdx.x < 72) w1[threadIdx.x] = Wg[j * 72 + threadIdx.x];
    else if (threadIdx.x < 144) w2[threadIdx.x - 72] = Wg[(16 + j) * 72 + threadIdx.x - 72];
    __syncthreads();
    float b1 = bg[j], b2 = bg[16 + j];
    const float* x1p = X + ((size_t)b * CC + j * 8) * PP;
    const float* x2p = X + ((size_t)b * CC + (16 + j) * 8) * PP;
    for (int p = p0 + threadIdx.x; p < p0 + 512; p += 256) {
        int h = p >> 6, wq = p & 63;
        float t1 = b1, t2 = b2;
        for (int ci = 0; ci < 8; ci++) {
#pragma unroll
            for (int kh = 0; kh < 3; kh++) {
                int hh = h + kh - 1;
                if ((unsigned)hh >= (unsigned)HH) continue;
#pragma unroll
                for (int kw = 0; kw < 3; kw++) {
                    int wc = wq + kw - 1;
                    if ((unsigned)wc >= (unsigned)WW) continue;
                    float xv1 = x1p[(size_t)ci * PP + hh * WW + wc];
                    float xv2 = x2p[(size_t)ci * PP + hh * WW + wc];
                    t1 += xv1 * w1[ci * 9 + kh * 3 + kw];
                    t2 += xv2 * w2[ci * 9 + kh * 3 + kw];
                }
            }
        }
        TG[((size_t)b * 16 + j) * PP + p] = t1 * t2;
    }
}

// ---------------- att = (conv1x1(tg,c2b)+b)*gamma + attlin ----------------
__global__ void __launch_bounds__(256) att_mix(const float* __restrict__ TG,
                                               const float* __restrict__ c2bw,
                                               const float* __restrict__ c2bb,
                                               const float* __restrict__ attg,
                                               const float* __restrict__ ATTLIN,
                                               float* __restrict__ ATT) {
    int n = blockIdx.x;
    int b = blockIdx.z;
    int p0 = blockIdx.y * 1024;
    float wr[16];
#pragma unroll
    for (int q = 0; q < 16; q++) wr[q] = c2bw[n * 16 + q];
    float bb = c2bb[n], gam = attg[n];
    const float* tgb = TG + (size_t)b * 16 * PP;
    size_t base = ((size_t)b * NSET + n) * PP;
    for (int p = p0 + threadIdx.x; p < p0 + 1024; p += 256) {
        float s = bb;
#pragma unroll
        for (int q = 0; q < 16; q++) s += tgb[(size_t)q * PP + p] * wr[q];
        ATT[base + p] = s * gam + ATTLIN[base + p];
    }
}

// =========================================================================
// IKBA via warp-level tf32 mma.sync (m16n8k8).
// Block = (group, 2 H-rows = 128 pixels, batch). 128 threads = 4 warps.
// A [M=128 pixels x K=128 nset] smem stride 133 (tf32 bits)
// B [N=56 x K=128] smem stride 132: rows 0-47 w_cb cols gr*48.., rows 48-51
//   b_cb channels gr*4.. (horizontal pass only), rows 52-55 zero.
// Warp w computes rows 32w..32w+31 x all 56 cols (2 x 7 mma tiles).
// Epilogue: D -> smem (stride 57), thread=pixel applies 12-tap matvec.
// =========================================================================
#define IKBA_SMEM_FLOATS (128 * 133 + 56 * 132)

template <int VERT>
__global__ void __launch_bounds__(128) ikba_mma(const float* __restrict__ ATT,
                                                const float* __restrict__ wcb,
                                                const float* __restrict__ bcb,
                                                const float* __restrict__ ga1,
                                                const float* __restrict__ SRC,
                                                const float* __restrict__ UFR,
                                                float* __restrict__ OUT,
                                                int halfoff) {
    extern __shared__ float sm[];
    uint32_t* Asu = (uint32_t*)sm;              // [128][133]
    uint32_t* Bsu = (uint32_t*)(sm + 128 * 133); // [56][132]
    float* Cs = sm;                              // alias post-GEMM: [128][57]

    int gr = blockIdx.x, h2 = blockIdx.y, b = blockIdx.z;
    int tid = threadIdx.x;

    // ---- A fill: thread = pixel, loop k (coalesced LDG, conflict-free STS)
    {
        const float* ap = ATT + (size_t)b * NSET * PP + (size_t)h2 * 128 + tid;
#pragma unroll 4
        for (int k = 0; k < 128; k++)
            Asu[tid * 133 + k] = f2tf(ap[(size_t)k * PP]);
    }
    // ---- B fill: rows 0..47 from w_cb (coalesced over n)
    for (int l = tid; l < 48 * 128; l += 128) {
        int k = l / 48, n = l - k * 48;
        Bsu[n * 132 + k] = f2tf(wcb[halfoff + (size_t)k * 6144 + gr * 48 + n]);
    }
    // ---- B rows 48..55: bias (horizontal) / zero
    for (int l = tid; l < 8 * 128; l += 128) {
        int k = l >> 3, n = 48 + (l & 7);
        float v = 0.f;
        if (!VERT && n < 52) v = bcb[k * CC + gr * CGC + (n - 48)];
        Bsu[n * 132 + k] = f2tf(v);
    }
    __syncthreads();

    int warp = tid >> 5, lane = tid & 31;
    int qr = lane >> 2, l4 = lane & 3;      // qr: m-row / n-col part, l4: k part
    int m_base = warp << 5;
    float acc[2][7][4];
#pragma unroll
    for (int i = 0; i < 2; i++)
#pragma unroll
        for (int j = 0; j < 7; j++)
#pragma unroll
            for (int t = 0; t < 4; t++) acc[i][j][t] = 0.f;

    for (int k0 = 0; k0 < 128; k0 += 8) {
        uint32_t a[2][4];
#pragma unroll
        for (int mt = 0; mt < 2; mt++) {
            int base = (m_base + mt * 16 + qr) * 133 + k0 + l4;
            a[mt][0] = Asu[base];
            a[mt][1] = Asu[base + 8 * 133];
            a[mt][2] = Asu[base + 4];
            a[mt][3] = Asu[base + 8 * 133 + 4];
        }
#pragma unroll
        for (int nt = 0; nt < 7; nt++) {
            uint32_t b0 = Bsu[(nt * 8 + qr) * 132 + k0 + l4];
            uint32_t b1 = Bsu[(nt * 8 + qr) * 132 + k0 + l4 + 4];
#pragma unroll
            for (int mt = 0; mt < 2; mt++) {
                asm volatile(
                    "mma.sync.aligned.m16n8k8.row.col.f32.tf32.tf32.f32 "
                    "{%0,%1,%2,%3}, {%4,%5,%6,%7}, {%8,%9}, {%0,%1,%2,%3};"
                    : "+f"(acc[mt][nt][0]), "+f"(acc[mt][nt][1]),
                      "+f"(acc[mt][nt][2]), "+f"(acc[mt][nt][3])
                    : "r"(a[mt][0]), "r"(a[mt][1]), "r"(a[mt][2]), "r"(a[mt][3]),
                      "r"(b0), "r"(b1));
            }
        }
    }
    __syncthreads();   // all Asu reads done before alias overwrite

    // ---- store D tile: c0/c1 at (row, 2*l4 + nt*8), c2/c3 at row+8
#pragma unroll
    for (int mt = 0; mt < 2; mt++)
#pragma unroll
        for (int nt = 0; nt < 7; nt++) {
            int r = m_base + mt * 16 + qr;
            int cl = nt * 8 + 2 * l4;
            Cs[r * 57 + cl]           = acc[mt][nt][0];
            Cs[r * 57 + cl + 1]       = acc[mt][nt][1];
            Cs[(r + 8) * 57 + cl]     = acc[mt][nt][2];
            Cs[(r + 8) * 57 + cl + 1] = acc[mt][nt][3];
        }
    __syncthreads();

    // ---- epilogue: thread = pixel
    int pix = tid, r0 = pix >> 6, cp = pix & 63;
    int h = h2 * 2 + r0;
    float uf[12];
    size_t srcBase = (size_t)(b * CC + gr * CGC) * PP;
#pragma unroll
    for (int ci = 0; ci < 4; ci++)
#pragma unroll
        for (int tap = 0; tap < 3; tap++) {
            float v = 0.f;
            if (VERT) {
                int hh = h + tap - 1;
                if ((unsigned)hh < (unsigned)HH)
                    v = SRC[srcBase + (size_t)ci * PP + hh * WW + cp];
            } else {
                int wc = cp + tap - 1;
                if ((unsigned)wc < (unsigned)WW)
                    v = SRC[srcBase + (size_t)ci * PP + h * WW + wc];
            }
            uf[ci * 3 + tap] = v;
        }
    const float* cpr = &Cs[pix * 57];
#pragma unroll
    for (int oi = 0; oi < 4; oi++) {
        float s = 0.f;
#pragma unroll
        for (int j = 0; j < 12; j++) s += cpr[oi * 12 + j] * uf[j];
        size_t oidx = (size_t)(b * CC + gr * CGC + oi) * PP + (size_t)h2 * 128 + pix;
        if (VERT) {
            OUT[oidx] = s;
        } else {
            s += cpr[48 + oi];
            OUT[oidx] = s * ga1[gr * CGC + oi] + UFR[oidx];
        }
    }
}

// ---------------- launch ----------------
extern "C" void kernel_launch(void* const* d_in, const int* in_sizes, int n_in,
                              void* d_out, int out_size) {
    const float* x       = (const float*)d_in[0];
    const float* dw1_w   = (const float*)d_in[1];
    const float* dw2_w   = (const float*)d_in[2];
    const float* proj_w  = (const float*)d_in[3];
    const float* lka0_w  = (const float*)d_in[4];
    const float* lkas_w  = (const float*)d_in[5];
    const float* lka1_w  = (const float*)d_in[6];
    const float* lka1_b  = (const float*)d_in[7];
    const float* sca_w   = (const float*)d_in[8];
    const float* sca_b   = (const float*)d_in[9];
    const float* c1a_w   = (const float*)d_in[10];
    const float* c1b_w   = (const float*)d_in[11];
    const float* c2a_w   = (const float*)d_in[12];
    const float* c2a_b   = (const float*)d_in[13];
    const float* c2b_w   = (const float*)d_in[14];
    const float* c2b_b   = (const float*)d_in[15];
    const float* c211_w  = (const float*)d_in[16];
    const float* c211_b  = (const float*)d_in[17];
    const float* w_cb    = (const float*)d_in[18];
    const float* b_cb    = (const float*)d_in[19];
    const float* attgam  = (const float*)d_in[20];
    const float* ga1     = (const float*)d_in[21];
    float* out = (float*)d_out;

    float *meanb, *scab, *ydw1, *yc1a, *attlin, *x1b, *ufb, *l0, *l1,
          *tg, *att, *xh, *x2b, *zb;
    cudaGetSymbolAddress((void**)&meanb, g_mean);
    cudaGetSymbolAddress((void**)&scab, g_sca);
    cudaGetSymbolAddress((void**)&ydw1, g_ydw1);
    cudaGetSymbolAddress((void**)&yc1a, g_yc1a);
    cudaGetSymbolAddress((void**)&attlin, g_attlin);
    cudaGetSymbolAddress((void**)&x1b, g_x1);
    cudaGetSymbolAddress((void**)&ufb, g_uf);
    cudaGetSymbolAddress((void**)&l0, g_l0);
    cudaGetSymbolAddress((void**)&l1, g_l1);
    cudaGetSymbolAddress((void**)&tg, g_tg);
    cudaGetSymbolAddress((void**)&att, g_att);
    cudaGetSymbolAddress((void**)&xh, g_xh);
    cudaGetSymbolAddress((void**)&x2b, g_x2);
    cudaGetSymbolAddress((void**)&zb, g_z);

    // channel-attention branch
    meankern<<<BB * CC, 256>>>(x, meanb);
    scakern<<<BB, 256>>>(meanb, sca_w, sca_b, scab);

    // 1x1 convs from x, batched (dw1 -> ydw1, c1a -> yc1a, c211 -> attlin)
    gemm3<<<dim3(64, 10, BB), 256>>>(dw1_w, c1a_w, c211_w, c211_b, x,
                                     ydw1, yc1a, attlin);

    // depthwise chains
    dwconv<3, 1, 1><<<BB * CC, 256>>>(ydw1, dw2_w, x1b);
    dwconv<3, 1, 1><<<BB * CC, 256>>>(yc1a, c1b_w, ufb);
    dwconv<5, 1, 2><<<BB * CC, 256>>>(x, lka0_w, l0);
    dwconv<7, 3, 9><<<BB * CC, 256>>>(l0, lkas_w, l1);

    // attention map
    c2a_gate<<<dim3(BB * 16, 8), 256>>>(x, c2a_w, c2a_b, tg);
    att_mix<<<dim3(NSET, 4, BB), 256>>>(tg, c2b_w, c2b_b, attgam, attlin, att);

    // IKBA via tf32 mma.sync
    size_t shmem = IKBA_SMEM_FLOATS * sizeof(float);
    cudaFuncSetAttribute(ikba_mma<1>, cudaFuncAttributeMaxDynamicSharedMemorySize,
                         (int)shmem);
    cudaFuncSetAttribute(ikba_mma<0>, cudaFuncAttributeMaxDynamicSharedMemorySize,
                         (int)shmem);
    ikba_mma<1><<<dim3(GG, 32, BB), 128, shmem>>>(att, w_cb, b_cb, ga1,
                                                  ufb, nullptr, xh, 0);
    ikba_mma<0><<<dim3(GG, 32, BB), 128, shmem>>>(att, w_cb, b_cb, ga1,
                                                  xh, ufb, x2b, 3072);

    // lka1 GEMM with fused elementwise merge: z = (W@l1+b)*x1*x2*sca
    gemm_lka_ew<<<dim3(64, 4, BB), 256>>>(lka1_w, l1, lka1_b, x1b, x2b, scab, zb);

    // final projection
    gemm1x1<<<dim3(64, 4, BB), 256>>>(proj_w, zb, nullptr, out, 256, 256);
}